// round 2
// baseline (speedup 1.0000x reference)
#include <cuda_runtime.h>
#include <cuda_bf16.h>
#include <math.h>

// LandmarkLoss: B=16, N=4096, flow [B,2,W,H] with W=H=1024.
// loss = sum over valid points of (x1+o0-x2)^2 + (y1+o1-y2)^2, / (2B)
// Reference's EXACT (non-standard) bilinear weights:
//   wa = (x1-x1d)*(y1-y1d)
//   wb = (x1u-x1)*(y1u-x1)   <- uses x1, faithful to source
//   wc = (x1u-x1)*(y1-y1d)
//   wd = (x1-x1d)*(y1u-x1)   <- uses x1, faithful to source
//
// R2: 2 threads per point (channel split, pp = dx^2 + dy^2 decomposes),
// single balanced wave (296 blocks x 448 thr = 2 blocks/SM on 148 SMs),
// single kernel node: last-block reduction via device scratch + ticket.

#define LB 16
#define LN 4096
#define LW 1024
#define LH 1024

#define NBLOCKS 296
#define NTHREADS 448           // 14 warps
#define TOTAL (2 * LB * LN)    // 131072 work items (point x channel)

__device__ float ll_partials[NBLOCKS];
__device__ unsigned int ll_ticket = 0;

__global__ __launch_bounds__(NTHREADS) void ll_loss_kernel(
    const float* __restrict__ lm,     // [B,N,4]
    const float* __restrict__ flow,   // [B,2,W,H]
    float* __restrict__ out)
{
    int j = blockIdx.x * NTHREADS + threadIdx.x;
    float acc = 0.0f;

    if (j < TOTAL) {
        int i = j >> 1;          // point index
        int c = j & 1;           // channel
        int b = i >> 12;         // / LN

        float4 l = reinterpret_cast<const float4*>(lm)[i];
        float x1 = l.x, y1 = l.y;

        float x1d = floorf(x1);
        float y1d = floorf(y1);
        float x1u = x1d + 1.0f;
        float y1u = y1d + 1.0f;

        bool valid = (x1u < (float)LW) && (y1u < (float)LH);

        int xd = (int)x1d; xd = max(0, min(xd, LW - 2));
        int yd = (int)y1d; yd = max(0, min(yd, LH - 2));

        const float* f = flow + ((size_t)b * 2 + c) * (LW * LH);

        int idx_dd = xd * LH + yd;    // (xd, yd)
        int idx_du = idx_dd + 1;      // (xd, yu)
        int idx_ud = idx_dd + LH;     // (xu, yd)
        int idx_uu = idx_ud + 1;      // (xu, yu)

        // All 4 gathers up-front for MLP.
        float va = __ldg(f + idx_dd);
        float vb = __ldg(f + idx_uu);
        float vc = __ldg(f + idx_ud);
        float vd = __ldg(f + idx_du);

        float wa = (x1 - x1d) * (y1 - y1d);
        float wb = (x1u - x1) * (y1u - x1);  // faithful to source
        float wc = (x1u - x1) * (y1 - y1d);
        float wd = (x1 - x1d) * (y1u - x1);  // faithful to source

        float o = va * wa + vb * wb + vc * wc + vd * wd;

        // dc = (c==0 ? x1 - x2 : y1 - y2) + o
        float base = c ? (y1 - l.w) : (x1 - l.z);
        float dc = base + o;
        acc = valid ? dc * dc : 0.0f;
    }

    // ---- block reduction (14 warps) ----
    #pragma unroll
    for (int o = 16; o > 0; o >>= 1)
        acc += __shfl_down_sync(0xFFFFFFFFu, acc, o);

    __shared__ float s[NTHREADS / 32];
    __shared__ bool is_last;
    int lane = threadIdx.x & 31;
    int wid  = threadIdx.x >> 5;
    if (lane == 0) s[wid] = acc;
    __syncthreads();

    if (threadIdx.x == 0) {
        float bs = 0.0f;
        #pragma unroll
        for (int w = 0; w < NTHREADS / 32; w++) bs += s[w];
        ll_partials[blockIdx.x] = bs;
        __threadfence();
        unsigned int t = atomicAdd(&ll_ticket, 1u);
        is_last = (t == NBLOCKS - 1);
    }
    __syncthreads();

    // ---- last block: final reduction over 296 partials ----
    if (is_last) {
        float v = (threadIdx.x < NBLOCKS) ? ll_partials[threadIdx.x] : 0.0f;
        #pragma unroll
        for (int o = 16; o > 0; o >>= 1)
            v += __shfl_down_sync(0xFFFFFFFFu, v, o);
        if (lane == 0) s[wid] = v;
        __syncthreads();
        if (threadIdx.x == 0) {
            float total = 0.0f;
            #pragma unroll
            for (int w = 0; w < NTHREADS / 32; w++) total += s[w];
            out[0] = total * (1.0f / (2.0f * (float)LB));
            ll_ticket = 0;   // reset for next graph replay
        }
    }
}

extern "C" void kernel_launch(void* const* d_in, const int* in_sizes, int n_in,
                              void* d_out, int out_size)
{
    const float* lm   = (const float*)d_in[0];  // landmarks [B,N,4]
    const float* flow = (const float*)d_in[1];  // flow [B,2,W,H]
    float* out = (float*)d_out;

    ll_loss_kernel<<<NBLOCKS, NTHREADS>>>(lm, flow, out);
}